// round 6
// baseline (speedup 1.0000x reference)
#include <cuda_runtime.h>
#include <math.h>

#define NN 20000
#define NE 320000
#define PI_D 3.14159265358979323846

enum { M_NONE=0, M_SILU=1, M_ENV=2, M_RESID=3 };

// ---------------- scratch (static device globals; no allocation) -------------
__device__ float g_basis[16];
__device__ float g_wfo[128];
__device__ float g_feat[NE*40];
__device__ float g_x  [NE*128];
__device__ float g_t1 [NE*128];
__device__ float g_t2 [NE*128];
__device__ float g_env[NE];
__device__ float g_Y  [NE*9];
__device__ float g_V0 [NE*32];
__device__ float g_V1a[NE*96];
__device__ float g_V1b[NE*96];
__device__ float g_s  [NE*64];
__device__ float g_w2 [NE*32];
__device__ float g_agg[NN*288];
__device__ int   g_deg[NN];
__device__ int   g_off[NN+1];
__device__ int   g_cur[NN];
__device__ int   g_eid[NE];

// ---------------- packed f32x2 helpers ---------------------------------------
__device__ __forceinline__ void ffma2(unsigned long long& d,
                                      unsigned long long a,
                                      unsigned long long b) {
    asm("fma.rn.f32x2 %0, %1, %2, %0;" : "+l"(d) : "l"(a), "l"(b));
}
__device__ __forceinline__ unsigned long long pack2(float v) {
    unsigned u = __float_as_uint(v);
    return (unsigned long long)u * 0x100000001ULL;
}

// ---------------- init: basis trapz + fused w_f@w_out ------------------------
__global__ void k_init(const float* __restrict__ wf, const float* __restrict__ wout) {
    int tid = threadIdx.x;
    int k    = tid >> 5;
    int lane = tid & 31;
    if (k < 8) {
        double kk = (double)(k + 1);
        double h  = (1.0 - 1e-9) / 999.0;
        double s = 0.0;
        for (int i = lane; i < 1000; i += 32) {
            double r = 1e-9 + h * (double)i;
            s += sqrt(2.0) * sin(PI_D * kk * r) / r;
        }
        #pragma unroll
        for (int off = 16; off; off >>= 1) s += __shfl_xor_sync(0xffffffffu, s, off);
        double r0 = 1e-9, r9 = 1e-9 + h * 999.0;
        double b0 = sqrt(2.0) * sin(PI_D * kk * r0) / r0;
        double b9 = sqrt(2.0) * sin(PI_D * kk * r9) / r9;
        double mu = h * (s - 0.5 * (b0 + b9));
        double q = 0.0;
        for (int i = lane; i < 1000; i += 32) {
            double r = 1e-9 + h * (double)i;
            double b = sqrt(2.0) * sin(PI_D * kk * r) / r;
            double dd = b - mu;
            q += dd * dd;
        }
        #pragma unroll
        for (int off = 16; off; off >>= 1) q += __shfl_xor_sync(0xffffffffu, q, off);
        double q0 = (b0 - mu) * (b0 - mu), q9 = (b9 - mu) * (b9 - mu);
        double s2 = h * (q - 0.5 * (q0 + q9));
        if (lane == 0) {
            g_basis[k]     = (float)mu;
            g_basis[8 + k] = (float)sqrt(s2);
        }
    }
    if (tid < 128) {
        float s = 0.f;
        for (int j = 0; j < 128; j++) s += wf[tid*128 + j] * wout[j];
        g_wfo[tid] = s * (1.0f / 128.0f);
    }
}

// ---------------- per-edge features ------------------------------------------
__global__ void k_feat(const float* __restrict__ ev, const float* __restrict__ attrs,
                       const int* __restrict__ src, const int* __restrict__ dst) {
    int e = blockIdx.x * blockDim.x + threadIdx.x;
    if (e >= NE) return;
    float x = ev[e*3+0], y = ev[e*3+1], z = ev[e*3+2];
    float d2 = x*x + y*y + z*z;
    float d  = sqrtf(d2 == 0.f ? 1.f : d2);
    const float SQ2 = 1.41421356237309515f;
    #pragma unroll
    for (int k = 0; k < 8; k++) {
        float b = SQ2 * sinf(3.14159265358979f * (float)(k+1) * d) / d;
        g_feat[e*40 + k] = (b - g_basis[k]) / g_basis[8 + k];
    }
    int s = src[e], t = dst[e];
    {
        const float4* pa = (const float4*)&attrs[s*16];
        const float4* pb = (const float4*)&attrs[t*16];
        float4* oa = (float4*)&g_feat[e*40 + 8];
        float4* ob = (float4*)&g_feat[e*40 + 24];
        #pragma unroll
        for (int q = 0; q < 4; q++) oa[q] = pa[q];
        #pragma unroll
        for (int q = 0; q < 4; q++) ob[q] = pb[q];
    }
    float d6 = d2*d2*d2, d7 = d6*d, d8 = d7*d;
    g_env[e] = 1.0f - 28.0f*d6 + 48.0f*d7 - 21.0f*d8;
    float inv = 1.0f / d;
    float rx = x*inv, ry = y*inv, rz = z*inv;
    const float s3  = 1.7320508075688772f;
    const float s15 = 3.872983346207417f;
    const float s5  = 2.2360679774997896f;
    g_Y[e*9+0] = 1.0f;
    g_Y[e*9+1] = s3*rx;  g_Y[e*9+2] = s3*ry;  g_Y[e*9+3] = s3*rz;
    g_Y[e*9+4] = s15*rx*ry;
    g_Y[e*9+5] = s15*ry*rz;
    g_Y[e*9+6] = 0.5f*s5*(3.0f*rz*rz - 1.0f);
    g_Y[e*9+7] = s15*rx*rz;
    g_Y[e*9+8] = 0.5f*s15*(rx*rx - ry*ry);
}

// ---------------- CSR build ---------------------------------------------------
__global__ void k_count(const int* __restrict__ src) {
    int e = blockIdx.x * blockDim.x + threadIdx.x;
    if (e < NE) atomicAdd(&g_deg[src[e]], 1);
}
__global__ void k_scan() {
    __shared__ int partial[256];
    int t = threadIdx.x;
    const int CH = (NN + 255) / 256;
    int lo = t * CH, hi = min(lo + CH, NN);
    int s = 0;
    for (int i = lo; i < hi; i++) s += g_deg[i];
    partial[t] = s;
    __syncthreads();
    if (t == 0) {
        int run = 0;
        for (int i = 0; i < 256; i++) { int v = partial[i]; partial[i] = run; run += v; }
    }
    __syncthreads();
    int run = partial[t];
    for (int i = lo; i < hi; i++) {
        int dgr = g_deg[i];
        g_off[i] = run; g_cur[i] = run;
        run += dgr;
    }
    if (t == 255) g_off[NN] = run;
}
__global__ void k_fill(const int* __restrict__ src) {
    int e = blockIdx.x * blockDim.x + threadIdx.x;
    if (e >= NE) return;
    int pos = atomicAdd(&g_cur[src[e]], 1);
    g_eid[pos] = e;
}

// ---------------- aggregation: warp per node, lane = channel ------------------
__global__ void k_agg() {
    int n = blockIdx.x * (blockDim.x >> 5) + (threadIdx.x >> 5);
    int c = threadIdx.x & 31;
    if (n >= NN) return;
    int lo = g_off[n], hi = g_off[n+1];
    float acc[9];
    #pragma unroll
    for (int m = 0; m < 9; m++) acc[m] = 0.f;
    for (int k = lo; k < hi; k++) {
        int e = __ldg(&g_eid[k]);
        float w = __ldg(&g_w2[e*32 + c]);
        const float* ye = &g_Y[e*9];
        #pragma unroll
        for (int m = 0; m < 9; m++) acc[m] += w * __ldg(&ye[m]);
    }
    float* o = &g_agg[n*288 + c*9];
    #pragma unroll
    for (int m = 0; m < 9; m++) o[m] = acc[m];
}

// ---------------- register-tiled GEMM: 64 edges/block, 256 threads -----------
// Thread owns OT outputs x ET edges. Per k: ET/4 (or fewer) edge vector loads
// + OT broadcast LDS.32 weight loads feed OT*ET/2 FFMA2 -> far fewer smem
// wavefronts per MAC than one-output-per-thread.
template<int IA, int IB, int O, int MODE>
__global__ void __launch_bounds__(256)
k_gemm(const float* __restrict__ A, const float* __restrict__ B,
       const float* __restrict__ W, float* __restrict__ out) {
    constexpr int I    = IA + IB;
    constexpr int T    = 64;
    constexpr int NT   = 256;
    constexpr int OT   = (O >= 64) ? 4 : 2;       // outputs per thread
    constexpr int ET   = (T * O / NT) / OT;       // edges per thread (2,4,8)
    constexpr int OSTR = O / OT;                  // output stride
    constexpr int LD   = T + 4;                   // 68
    extern __shared__ float sm[];
    float* in_s = sm;             // I * LD, feature-major
    float* W_s  = sm + I * LD;    // I * O

    int tid = threadIdx.x;
    int e0  = blockIdx.x * T;

    for (int i = tid; i < I * O; i += NT) W_s[i] = W[i];
    for (int i = tid; i < T * IA; i += NT) {
        int e = i / IA, f = i % IA;
        in_s[f * LD + e] = A[(size_t)(e0 + e) * IA + f];
    }
    if (IB > 0) {
        for (int i = tid; i < T * IB; i += NT) {
            int e = i / IB, f = i % IB;
            in_s[(IA + f) * LD + e] = B[(size_t)(e0 + e) * IB + f];
        }
    }
    __syncthreads();

    int oq    = tid % OSTR;
    int ebase = (tid / OSTR) * ET;

    unsigned long long acc2[OT][ET/2];
    #pragma unroll
    for (int i = 0; i < OT; i++)
        #pragma unroll
        for (int j = 0; j < ET/2; j++) acc2[i][j] = 0ULL;

    #pragma unroll 2
    for (int k = 0; k < I; k++) {
        unsigned long long ed[ET/2];
        const float* ebp = &in_s[k * LD + ebase];
        if constexpr (ET == 2) {
            ed[0] = *(const unsigned long long*)ebp;
        } else if constexpr (ET == 4) {
            ulonglong2 v = *(const ulonglong2*)ebp;
            ed[0] = v.x; ed[1] = v.y;
        } else {
            ulonglong2 v0 = ((const ulonglong2*)ebp)[0];
            ulonglong2 v1 = ((const ulonglong2*)ebp)[1];
            ed[0] = v0.x; ed[1] = v0.y; ed[2] = v1.x; ed[3] = v1.y;
        }
        unsigned long long wp[OT];
        #pragma unroll
        for (int i = 0; i < OT; i++) wp[i] = pack2(W_s[k * O + oq + OSTR * i]);
        #pragma unroll
        for (int i = 0; i < OT; i++)
            #pragma unroll
            for (int j = 0; j < ET/2; j++)
                ffma2(acc2[i][j], ed[j], wp[i]);
    }

    float scale = 1.0f / sqrtf((float)I);
    const float rs = 0.8944271909999159f;  // 1/sqrt(1.25)
    #pragma unroll
    for (int i = 0; i < OT; i++) {
        int o = oq + OSTR * i;
        #pragma unroll
        for (int j = 0; j < ET/2; j++) {
            float2 f2 = *(float2*)&acc2[i][j];
            #pragma unroll
            for (int h = 0; h < 2; h++) {
                int e = e0 + ebase + 2*j + h;
                float v = (h ? f2.y : f2.x) * scale;
                if (MODE == M_SILU)  v = v / (1.0f + __expf(-v));
                if (MODE == M_ENV)   v = v * g_env[e];
                if (MODE == M_RESID) v = (g_x[(size_t)e*128 + o] + 0.5f * g_env[e] * v) * rs;
                out[(size_t)e * O + o] = v;
            }
        }
    }
}

// ---------------- per-layer: scalars s + vector mixing -----------------------
// Phase 2 restructured: lane = edge (distinct LDS.32 Vm reads), thread owns
// 8 channels (4 f32x2 pairs) x 3 components. Output bounced through smem so
// global stores coalesce.
template<int L1>
__global__ void k_pre(const int* __restrict__ src, const float* __restrict__ lin,
                      const float* __restrict__ V1in, float* __restrict__ V1out) {
    constexpr int M  = L1 ? 96 : 64;
    constexpr int LD = 36;
    constexpr int VLD = 97;                 // V1s row stride (conflict-free STS)
    extern __shared__ float sm[];
    float* Vm    = sm;                      // 3*M*LD
    float* lin_s = sm + 3*M*LD;             // M*32
    float* V1s   = lin_s + M*32;            // 32*VLD

    int tid = threadIdx.x;
    int e0  = blockIdx.x * 32;
    for (int i = tid; i < M * 32; i += 128) lin_s[i] = lin[i];

    int c = tid & 31, eg = tid >> 5;
    const float s15h = 1.9364916731037085f;
    const float s5h  = 1.1180339887498949f;
    const float s5   = 2.2360679774997896f;
    const float itp  = 0.28284271247461906f; // 1/sqrt(12.5)
    const float is3  = 0.5773502691896258f;  // 1/sqrt(3)

    for (int j = 0; j < 8; j++) {
        int el = eg * 8 + j;
        int e  = e0 + el;
        int sn = src[e];
        const float* ag = &g_agg[sn * 288 + c * 9];
        float A0  = ag[0]*0.25f;
        float A1x = ag[1]*0.25f, A1y = ag[2]*0.25f, A1z = ag[3]*0.25f;
        float axy = ag[4]*0.25f, ayz = ag[5]*0.25f, az2 = ag[6]*0.25f;
        float axz = ag[7]*0.25f, ax2 = ag[8]*0.25f;
        float vx, vy, vz, v0 = 0.f;
        if (L1) {
            v0 = g_V0[e*32 + c];
            vx = v0 * g_Y[e*9+1];
            vy = v0 * g_Y[e*9+2];
            vz = v0 * g_Y[e*9+3];
        } else {
            vx = V1in[e*96 + c*3 + 0];
            vy = V1in[e*96 + c*3 + 1];
            vz = V1in[e*96 + c*3 + 2];
        }
        float sc1 = (A1x*vx + A1y*vy + A1z*vz) * is3;
        if (L1) {
            g_s[e*64 + c*2 + 0] = A0 * v0;
            g_s[e*64 + c*2 + 1] = sc1;
            Vm[(0*M + 32 + c)*LD + el] = A1x * v0;
            Vm[(1*M + 32 + c)*LD + el] = A1y * v0;
            Vm[(2*M + 32 + c)*LD + el] = A1z * v0;
        } else {
            g_s[e*32 + c] = sc1;
        }
        Vm[(0*M + c)*LD + el] = A0 * vx;
        Vm[(1*M + c)*LD + el] = A0 * vy;
        Vm[(2*M + c)*LD + el] = A0 * vz;
        float mxx = -s5h*az2 + s15h*ax2;
        float myy = -s5h*az2 - s15h*ax2;
        float mzz =  s5 * az2;
        float mxy = s15h*axy, mxz = s15h*axz, myz = s15h*ayz;
        int toff = L1 ? 64 : 32;
        Vm[(0*M + toff + c)*LD + el] = (mxx*vx + mxy*vy + mxz*vz) * itp;
        Vm[(1*M + toff + c)*LD + el] = (mxy*vx + myy*vy + myz*vz) * itp;
        Vm[(2*M + toff + c)*LD + el] = (mxz*vx + myz*vy + mzz*vz) * itp;
    }
    __syncthreads();

    // phase 2: lane = edge; warp covers channels [w*8, w*8+8)
    {
        int lane = tid & 31;          // edge
        int cb   = (tid >> 5) * 8;    // channel base
        unsigned long long acc2[3][4];
        #pragma unroll
        for (int t = 0; t < 3; t++)
            #pragma unroll
            for (int p = 0; p < 4; p++) acc2[t][p] = 0ULL;

        #pragma unroll 2
        for (int m = 0; m < M; m++) {
            unsigned long long vmp[3];
            #pragma unroll
            for (int t = 0; t < 3; t++)
                vmp[t] = pack2(Vm[(t*M + m)*LD + lane]);
            #pragma unroll
            for (int p = 0; p < 4; p++) {
                unsigned long long lp =
                    *(const unsigned long long*)&lin_s[m*32 + cb + 2*p];
                ffma2(acc2[0][p], lp, vmp[0]);
                ffma2(acc2[1][p], lp, vmp[1]);
                ffma2(acc2[2][p], lp, vmp[2]);
            }
        }
        float scv = 1.0f / sqrtf((float)M);
        #pragma unroll
        for (int p = 0; p < 4; p++) {
            int c0 = cb + 2*p;
            #pragma unroll
            for (int t = 0; t < 3; t++) {
                float2 f2 = *(float2*)&acc2[t][p];
                V1s[lane*VLD + c0*3 + t]       = f2.x * scv;
                V1s[lane*VLD + (c0+1)*3 + t]   = f2.y * scv;
            }
        }
    }
    __syncthreads();

    // coalesced copy out: 32*96 floats
    for (int r = 0; r < 24; r++) {
        int i = tid + 128 * r;
        int e = i / 96, f = i - e * 96;
        V1out[(size_t)(e0 + e) * 96 + f] = V1s[e * VLD + f];
    }
}

// ---------------- final: out = x . wfo ---------------------------------------
__global__ void k_final(float* __restrict__ out) {
    int gt = blockIdx.x * blockDim.x + threadIdx.x;
    int e  = gt >> 5;
    int lane = threadIdx.x & 31;
    if (e >= NE) return;
    const float* xr = &g_x[(size_t)e * 128];
    float s = xr[lane]      * g_wfo[lane]
            + xr[lane + 32] * g_wfo[lane + 32]
            + xr[lane + 64] * g_wfo[lane + 64]
            + xr[lane + 96] * g_wfo[lane + 96];
    #pragma unroll
    for (int off = 16; off; off >>= 1) s += __shfl_down_sync(0xffffffffu, s, off);
    if (lane == 0) out[e] = s;
}

// ---------------- host side ---------------------------------------------------
template<int IA, int IB, int O, int MODE>
static void launch_gemm(const float* A, const float* B, const float* W, float* out) {
    constexpr int I = IA + IB;
    size_t smem = (size_t)(I * 68 + I * O) * sizeof(float);
    cudaFuncSetAttribute(k_gemm<IA, IB, O, MODE>,
                         cudaFuncAttributeMaxDynamicSharedMemorySize, (int)smem);
    k_gemm<IA, IB, O, MODE><<<NE / 64, 256, smem>>>(A, B, W, out);
}

extern "C" void kernel_launch(void* const* d_in, const int* in_sizes, int n_in,
                              void* d_out, int out_size) {
    const float* node_attrs = (const float*)d_in[0];
    const float* ev         = (const float*)d_in[1];
    const float* w_emb0     = (const float*)d_in[2];
    const float* w_emb1     = (const float*)d_in[3];
    const float* w_emb2     = (const float*)d_in[4];
    const float* w_emb3     = (const float*)d_in[5];
    const float* w_w0       = (const float*)d_in[6];
    const float* w_w[3]  = { (const float*)d_in[7],  (const float*)d_in[12], (const float*)d_in[17] };
    const float* lat0[3] = { (const float*)d_in[8],  (const float*)d_in[13], (const float*)d_in[18] };
    const float* lat1[3] = { (const float*)d_in[9],  (const float*)d_in[14], (const float*)d_in[19] };
    const float* lat2[3] = { (const float*)d_in[10], (const float*)d_in[15], (const float*)d_in[20] };
    const float* lin[3]  = { (const float*)d_in[11], (const float*)d_in[16], (const float*)d_in[21] };
    const float* w_f   = (const float*)d_in[22];
    const float* w_out = (const float*)d_in[23];
    const int*   src   = (const int*)d_in[24];
    const int*   dst   = (const int*)d_in[25];
    float* out = (float*)d_out;

    float *p_feat, *p_x, *p_t1, *p_t2, *p_V0, *p_V1a, *p_V1b, *p_s, *p_w2;
    int *p_deg;
    cudaGetSymbolAddress((void**)&p_feat, g_feat);
    cudaGetSymbolAddress((void**)&p_x,   g_x);
    cudaGetSymbolAddress((void**)&p_t1,  g_t1);
    cudaGetSymbolAddress((void**)&p_t2,  g_t2);
    cudaGetSymbolAddress((void**)&p_V0,  g_V0);
    cudaGetSymbolAddress((void**)&p_V1a, g_V1a);
    cudaGetSymbolAddress((void**)&p_V1b, g_V1b);
    cudaGetSymbolAddress((void**)&p_s,   g_s);
    cudaGetSymbolAddress((void**)&p_w2,  g_w2);
    cudaGetSymbolAddress((void**)&p_deg, g_deg);

    size_t sm1 = (size_t)(3*96*36 + 96*32 + 32*97) * sizeof(float);
    size_t sm0 = (size_t)(3*64*36 + 64*32 + 32*97) * sizeof(float);
    cudaFuncSetAttribute(k_pre<1>, cudaFuncAttributeMaxDynamicSharedMemorySize, (int)sm1);
    cudaFuncSetAttribute(k_pre<0>, cudaFuncAttributeMaxDynamicSharedMemorySize, (int)sm0);

    // Launch order: ncu -s 5 -c 1 lands on k_gemm<64,0,128,M_ENV> (idx 5).
    k_init<<<1, 256>>>(w_f, w_out);                                  // 0
    k_feat<<<(NE + 255) / 256, 256>>>(ev, node_attrs, src, dst);     // 1
    launch_gemm<40, 0, 16,  M_SILU>(p_feat, nullptr, w_emb0, p_t1);  // 2
    launch_gemm<16, 0, 32,  M_SILU>(p_t1,   nullptr, w_emb1, p_t2);  // 3
    launch_gemm<32, 0, 64,  M_SILU>(p_t2,   nullptr, w_emb2, p_t1);  // 4
    launch_gemm<64, 0, 128, M_ENV >(p_t1,   nullptr, w_emb3, p_x);   // 5 <- PROFILED

    cudaMemsetAsync(p_deg, 0, NN * sizeof(int));
    k_count<<<(NE + 255) / 256, 256>>>(src);
    k_scan<<<1, 256>>>();
    k_fill<<<(NE + 255) / 256, 256>>>(src);

    launch_gemm<128, 0, 32, M_NONE>(p_x, nullptr, w_w0, p_V0);

    float* vin  = p_V1a;
    float* vout = p_V1b;
    for (int l = 0; l < 3; l++) {
        launch_gemm<128, 0, 32, M_NONE>(p_x, nullptr, w_w[l], p_w2);
        k_agg<<<(NN + 7) / 8, 256>>>();
        if (l == 0) {
            k_pre<1><<<NE / 32, 128, sm1>>>(src, lin[l], vin, vout);
            launch_gemm<128, 64, 128, M_SILU>(p_x, p_s, lat0[l], p_t1);
        } else {
            k_pre<0><<<NE / 32, 128, sm0>>>(src, lin[l], vin, vout);
            launch_gemm<128, 32, 128, M_SILU>(p_x, p_s, lat0[l], p_t1);
        }
        launch_gemm<128, 0, 128, M_SILU >(p_t1, nullptr, lat1[l], p_t2);
        launch_gemm<128, 0, 128, M_RESID>(p_t2, nullptr, lat2[l], p_x);
        float* tmp = vin; vin = vout; vout = tmp;
    }

    k_final<<<(NE * 32 + 255) / 256, 256>>>(out);
    (void)in_sizes; (void)n_in; (void)out_size; (void)dst;
}